// round 4
// baseline (speedup 1.0000x reference)
#include <cuda_runtime.h>
#include <cuda_bf16.h>

#define NB 64
#define NS 500
#define NH 512
#define NV 3
#define NT 500
#define GRID 128
#define NTHR 256

// dynamic smem layout (floats):
// [0, 32768)       two 16x1024 ctx tile buffers
// [32768, 33280)   h2s
// [33280, 33296)   sc
// [33296, 33312)   wts
// [33312, 33316)   ctl {rscale, m, l, -}
// [33316, 33320)   lg
// LSTM phases reuse [0, 2688).
#define SMEM_FLOATS 33320
#define SMEM_BYTES  (SMEM_FLOATS * 4 + 96)

// ---------------- device state ----------------
__device__ __align__(16) float g_apart[2][NB][1024];
__device__ float g_m[NB][2];
__device__ float g_l[NB][2];
__device__ __align__(16) float g_h1[2][NB][NH];
__device__ __align__(16) float g_c1[NB][NH];
__device__ __align__(16) float g_h2[2][NB][NH];
__device__ __align__(16) float g_c2[NB][NH];
__device__ __align__(16) float g_E[NV][4][NH];
__device__ __align__(16) float g_B2[4][NH];
__device__ int g_idx[NB];

__device__ unsigned g_count = 0;
__device__ volatile unsigned g_epoch = 0;

__device__ __forceinline__ void gbar() {
    __threadfence();
    __syncthreads();
    if (threadIdx.x == 0) {
        unsigned e = g_epoch;
        if (atomicAdd(&g_count, 1) == GRID - 1) {
            g_count = 0;
            __threadfence();
            g_epoch = e + 1;
        } else {
            while (g_epoch == e) { __nanosleep(64); }
        }
        __threadfence();
    }
    __syncthreads();
}

__device__ __forceinline__ float2 ffma2(float2 a, float2 b, float2 c) {
    float2 d;
    asm("fma.rn.f32x2 %0, %1, %2, %3;"
        : "=l"(*reinterpret_cast<unsigned long long*>(&d))
        : "l"(*reinterpret_cast<unsigned long long*>(&a)),
          "l"(*reinterpret_cast<unsigned long long*>(&b)),
          "l"(*reinterpret_cast<unsigned long long*>(&c)));
    return d;
}

__device__ __forceinline__ float sigm(float x) { return 1.f / (1.f + expf(-x)); }

__device__ __forceinline__ void cpasync16(float* dst, const float* src) {
    unsigned sa = (unsigned)__cvta_generic_to_shared(dst);
    asm volatile("cp.async.cg.shared.global [%0], [%1], 16;" :: "r"(sa), "l"(src));
}

// ---------------- attention: cp.async-pipelined flash ----------------
__device__ void attn_phase(const float* __restrict__ ctx, const float* __restrict__ Wl,
                           const float* __restrict__ blv, float* __restrict__ out,
                           int t, int blk, float* smem) {
    int p = t & 1;
    int b = blk >> 1, h = blk & 1;
    int tid = threadIdx.x;
    int warp = tid >> 5, lane = tid & 31;
    float* tiles = smem;
    float* h2s = smem + 32768;
    float* sc  = smem + 33280;
    float* wts = smem + 33296;
    float* ctl = smem + 33312;
    float* lg  = smem + 33316;

    const float* h2g = g_h2[p][b];
    ((float2*)h2s)[tid] = ((const float2*)h2g)[tid];
    if (tid == 0) { ctl[1] = -1e30f; ctl[2] = 0.f; }

    // ---- logits / argmax / log_softmax for step t-1 ----
    if (h == 0 && t > 0) {
        if (warp < 3) {
            const float* wr = Wl + warp * 512;
            float s = 0.f;
            for (int i = lane; i < 512; i += 32) s += wr[i] * h2g[i];
            for (int o = 16; o; o >>= 1) s += __shfl_xor_sync(0xffffffffu, s, o);
            if (!lane) lg[warp] = s + blv[warp];
        }
        __syncthreads();
        if (tid == 0) {
            float l0 = lg[0], l1 = lg[1], l2 = lg[2];
            int bi = 0; float bv = l0;
            if (l1 > bv) { bv = l1; bi = 1; }
            if (l2 > bv) { bv = l2; bi = 2; }
            g_idx[b] = bi;
            float lse = bv + logf(expf(l0 - bv) + expf(l1 - bv) + expf(l2 - bv));
            float* o = out + ((size_t)b * NT + (t - 1)) * 3;
            o[0] = l0 - lse; o[1] = l1 - lse; o[2] = l2 - lse;
        }
        __syncthreads();
    }
    if (t >= NT) return;

    const float* gbase = ctx + ((size_t)(b * NS + h * 250)) * 1024;
    float4 acc = make_float4(0.f, 0.f, 0.f, 0.f);
    const int ntiles = 16;               // 15 x 16 rows + 1 x 10 rows

    // prefetch tile 0 (16 rows, contiguous 64KB)
    for (int c = tid; c < 16 * 256; c += 256)
        cpasync16(tiles + c * 4, gbase + c * 4);
    asm volatile("cp.async.commit_group;");

    for (int tt = 0; tt < ntiles; tt++) {
        int row0 = tt * 16;
        int cnt = (250 - row0 < 16) ? (250 - row0) : 16;
        float* tb = tiles + (tt & 1) * 16384;

        if (tt + 1 < ntiles) {
            int r1 = row0 + 16;
            int c1 = (250 - r1 < 16) ? (250 - r1) : 16;
            float* dst = tiles + ((tt + 1) & 1) * 16384;
            const float* src = gbase + (size_t)r1 * 1024;
            for (int c = tid; c < c1 * 256; c += 256)
                cpasync16(dst + c * 4, src + c * 4);
            asm volatile("cp.async.commit_group;");
            asm volatile("cp.async.wait_group 1;");
        } else {
            asm volatile("cp.async.wait_group 0;");
        }
        __syncthreads();

        // scores: warp w handles rows w, w+8
        for (int r = warp; r < cnt; r += 8) {
            const float4* row = (const float4*)(tb + r * 1024);
            const float4* hh = (const float4*)h2s;
            float s = 0.f;
#pragma unroll
            for (int i = 0; i < 8; i++) {
                float4 cv = row[lane + 32 * i];
                float4 hv = hh[lane + 32 * (i & 3)];
                s += cv.x * hv.x + cv.y * hv.y + cv.z * hv.z + cv.w * hv.w;
            }
            for (int o = 16; o; o >>= 1) s += __shfl_xor_sync(0xffffffffu, s, o);
            if (!lane) sc[r] = s;
        }
        __syncthreads();

        // warp 0: tile softmax bookkeeping
        if (warp == 0) {
            float sv = (lane < cnt) ? sc[lane] : -1e30f;
            float mt = sv;
            for (int o = 16; o; o >>= 1) mt = fmaxf(mt, __shfl_xor_sync(0xffffffffu, mt, o));
            float mprev = ctl[1];
            float mnew = fmaxf(mprev, mt);
            float r = __expf(mprev - mnew);
            float w = (lane < cnt) ? __expf(sv - mnew) : 0.f;
            if (lane < 16) wts[lane] = w;
            float ws = w;
            for (int o = 16; o; o >>= 1) ws += __shfl_xor_sync(0xffffffffu, ws, o);
            if (!lane) {
                ctl[0] = r;
                ctl[1] = mnew;
                ctl[2] = ctl[2] * r + ws;
            }
        }
        __syncthreads();

        // accumulate: thread owns dims [4*tid, 4*tid+4)
        float rs = ctl[0];
        acc.x *= rs; acc.y *= rs; acc.z *= rs; acc.w *= rs;
#pragma unroll
        for (int r = 0; r < 16; r++) {
            if (r < cnt) {
                float w = wts[r];
                float4 v = ((const float4*)(tb + r * 1024))[tid];
                acc.x += w * v.x; acc.y += w * v.y;
                acc.z += w * v.z; acc.w += w * v.w;
            }
        }
        __syncthreads();   // protect buffer + sc/wts reuse
    }

    ((float4*)g_apart[h][b])[tid] = acc;
    if (tid == 0) { g_m[b][h] = ctl[1]; g_l[b][h] = ctl[2]; }
}

// ---------------- LSTM phases (unchanged math) ----------------
__device__ void lstm1_phase(const float* __restrict__ W_ih0, const float* __restrict__ W_hh0,
                            int t, int cb, float* smem) {
    int p = t & 1, q = p ^ 1;
    int tid = threadIdx.x;
    float* s0s = smem;
    float* s1s = smem + 64;
    float (*xs)[64] = (float(*)[64])(smem + 128);
    float (*wsT)[16] = (float(*)[16])(smem + 2176);

    if (tid < 64) {
        float m0 = g_m[tid][0], m1 = g_m[tid][1];
        float M = fmaxf(m0, m1);
        float e0 = __expf(m0 - M), e1 = __expf(m1 - M);
        float L = g_l[tid][0] * e0 + g_l[tid][1] * e1;
        s0s[tid] = e0 / L; s1s[tid] = e1 / L;
    }
    int b = tid & 63, jj = tid >> 6;
    int j0 = cb * 4 + jj;
    int vv = g_idx[b];
    float2 a01 = make_float2(g_E[vv][0][j0], g_E[vv][1][j0]);
    float2 a23 = make_float2(g_E[vv][2][j0], g_E[vv][3][j0]);

    int bq = tid >> 2;
    int kg = (tid & 3) * 8;
    int e2 = tid * 2;
    int lr = e2 >> 5, kl = e2 & 31;
    int jjr = lr >> 2, gr = lr & 3;
    int rowr = gr * 512 + cb * 4 + jjr;

    for (int kt = 0; kt < 48; kt++) {
        int kb = kt * 32;
        __syncthreads();
        {
            int k = kb + kg;
            if (k < 1024) {
                float s0 = s0s[bq], s1 = s1s[bq];
                const float4* a0 = (const float4*)&g_apart[0][bq][k];
                const float4* a1 = (const float4*)&g_apart[1][bq][k];
#pragma unroll
                for (int i = 0; i < 2; i++) {
                    float4 x0 = a0[i], x1 = a1[i];
                    xs[kg + i * 4 + 0][bq] = s0 * x0.x + s1 * x1.x;
                    xs[kg + i * 4 + 1][bq] = s0 * x0.y + s1 * x1.y;
                    xs[kg + i * 4 + 2][bq] = s0 * x0.z + s1 * x1.z;
                    xs[kg + i * 4 + 3][bq] = s0 * x0.w + s1 * x1.w;
                }
            } else {
                const float4* hs = (const float4*)&g_h1[p][bq][k - 1024];
#pragma unroll
                for (int i = 0; i < 2; i++) {
                    float4 x0 = hs[i];
                    xs[kg + i * 4 + 0][bq] = x0.x; xs[kg + i * 4 + 1][bq] = x0.y;
                    xs[kg + i * 4 + 2][bq] = x0.z; xs[kg + i * 4 + 3][bq] = x0.w;
                }
            }
        }
        {
            float2 wv;
            if (kb < 1024) wv = *(const float2*)&W_ih0[(size_t)rowr * 1536 + 512 + kb + kl];
            else           wv = *(const float2*)&W_hh0[(size_t)rowr * 512 + (kb - 1024) + kl];
            wsT[kl][lr] = wv.x; wsT[kl + 1][lr] = wv.y;
        }
        __syncthreads();
#pragma unroll
        for (int k = 0; k < 32; k++) {
            float x = xs[k][b];
            float4 w4 = *(const float4*)&wsT[k][jj * 4];
            float2 xx = make_float2(x, x);
            a01 = ffma2(make_float2(w4.x, w4.y), xx, a01);
            a23 = ffma2(make_float2(w4.z, w4.w), xx, a23);
        }
    }
    float si = sigm(a01.x), sf = sigm(a01.y), so = sigm(a23.y);
    float tg = tanhf(a23.x);
    float cn = sf * g_c1[b][j0] + si * tg;
    float hn = so * tanhf(cn);
    g_c1[b][j0] = cn;
    g_h1[q][b][j0] = hn;
}

__device__ void lstm2_phase(const float* __restrict__ W_ih1, const float* __restrict__ W_hh1,
                            int t, int cb, float* smem) {
    int p = t & 1, q = p ^ 1;
    int tid = threadIdx.x;
    float (*xs)[64] = (float(*)[64])(smem + 128);
    float (*wsT)[16] = (float(*)[16])(smem + 2176);

    int b = tid & 63, jj = tid >> 6;
    int j0 = cb * 4 + jj;
    float2 a01 = make_float2(g_B2[0][j0], g_B2[1][j0]);
    float2 a23 = make_float2(g_B2[2][j0], g_B2[3][j0]);

    int bq = tid >> 2;
    int kg = (tid & 3) * 8;
    int e2 = tid * 2;
    int lr = e2 >> 5, kl = e2 & 31;
    int jjr = lr >> 2, gr = lr & 3;
    int rowr = gr * 512 + cb * 4 + jjr;

    for (int kt = 0; kt < 32; kt++) {
        int kb = kt * 32;
        __syncthreads();
        {
            int k = kb + kg;
            const float4* src = (k < 512) ? (const float4*)&g_h1[q][bq][k]
                                          : (const float4*)&g_h2[p][bq][k - 512];
#pragma unroll
            for (int i = 0; i < 2; i++) {
                float4 x0 = src[i];
                xs[kg + i * 4 + 0][bq] = x0.x; xs[kg + i * 4 + 1][bq] = x0.y;
                xs[kg + i * 4 + 2][bq] = x0.z; xs[kg + i * 4 + 3][bq] = x0.w;
            }
        }
        {
            float2 wv;
            if (kb < 512) wv = *(const float2*)&W_ih1[(size_t)rowr * 512 + kb + kl];
            else          wv = *(const float2*)&W_hh1[(size_t)rowr * 512 + (kb - 512) + kl];
            wsT[kl][lr] = wv.x; wsT[kl + 1][lr] = wv.y;
        }
        __syncthreads();
#pragma unroll
        for (int k = 0; k < 32; k++) {
            float x = xs[k][b];
            float4 w4 = *(const float4*)&wsT[k][jj * 4];
            float2 xx = make_float2(x, x);
            a01 = ffma2(make_float2(w4.x, w4.y), xx, a01);
            a23 = ffma2(make_float2(w4.z, w4.w), xx, a23);
        }
    }
    float si = sigm(a01.x), sf = sigm(a01.y), so = sigm(a23.y);
    float tg = tanhf(a23.x);
    float cn = sf * g_c2[b][j0] + si * tg;
    float hn = so * tanhf(cn);
    g_c2[b][j0] = cn;
    g_h2[q][b][j0] = hn;
}

// ---------------- persistent kernel ----------------
__global__ void __launch_bounds__(NTHR, 1)
k_persist(const float* __restrict__ ctx, const int* __restrict__ tgt,
          const float* __restrict__ h1_0, const float* __restrict__ c1_0,
          const float* __restrict__ h2_0, const float* __restrict__ c2_0,
          const float* __restrict__ emb,
          const float* __restrict__ W_ih0, const float* __restrict__ W_hh0,
          const float* __restrict__ b_ih0, const float* __restrict__ b_hh0,
          const float* __restrict__ W_ih1, const float* __restrict__ W_hh1,
          const float* __restrict__ b_ih1, const float* __restrict__ b_hh1,
          const float* __restrict__ Wl, const float* __restrict__ blv,
          float* __restrict__ out, int out_size) {
    extern __shared__ __align__(16) float smem[];
    int blk = blockIdx.x;
    int tid = threadIdx.x;
    int warp = tid >> 5, lane = tid & 31;

    // ---- setup ----
    {
        int gi = blk * NTHR + tid;
        ((float*)g_h1[0])[gi] = h1_0[gi];
        ((float*)g_c1)[gi]    = c1_0[gi];
        ((float*)g_h2[0])[gi] = h2_0[gi];
        ((float*)g_c2)[gi]    = c2_0[gi];
        if (gi < 4 * NH) ((float*)g_B2)[gi] = b_ih1[gi] + b_hh1[gi];
        if (blk == 0 && tid < NB) g_idx[tid] = tgt[tid * NT];
        for (int r = blk * 8 + warp; r < NV * 2048; r += GRID * 8) {
            int v = r / 2048, row = r % 2048;
            const float* wr = W_ih0 + (size_t)row * 1536;
            const float* ev = emb + v * 512;
            float s = 0.f;
            for (int i = lane; i < 512; i += 32) s += wr[i] * ev[i];
            for (int o = 16; o; o >>= 1) s += __shfl_xor_sync(0xffffffffu, s, o);
            if (!lane) g_E[v][row >> 9][row & 511] = s + b_ih0[row] + b_hh0[row];
        }
    }
    gbar();

    for (int t = 0; t <= NT; t++) {
        attn_phase(ctx, Wl, blv, out, t, blk, smem);
        if (t == NT) break;
        gbar();
        lstm1_phase(W_ih0, W_hh0, t, blk, smem);
        gbar();
        lstm2_phase(W_ih1, W_hh1, t, blk, smem);
        gbar();
    }

    if (out_size >= NB * NT * NV + NB * NT) {
        int i = blk * NTHR + tid;
        if (i < NB * NT) out[NB * NT * NV + i] = (float)tgt[i];
    }
}

// ---------------- launch ----------------
extern "C" void kernel_launch(void* const* d_in, const int* in_sizes, int n_in,
                              void* d_out, int out_size) {
    int off = (n_in >= 18) ? 0 : -1;
    const float* ctx   = (const float*)d_in[0];
    const int*   tgt   = (const int*)d_in[1];
    const float* h1_0  = (const float*)d_in[3 + off];
    const float* c1_0  = (const float*)d_in[4 + off];
    const float* h2_0  = (const float*)d_in[5 + off];
    const float* c2_0  = (const float*)d_in[6 + off];
    const float* emb   = (const float*)d_in[7 + off];
    const float* W_ih0 = (const float*)d_in[8 + off];
    const float* W_hh0 = (const float*)d_in[9 + off];
    const float* b_ih0 = (const float*)d_in[10 + off];
    const float* b_hh0 = (const float*)d_in[11 + off];
    const float* W_ih1 = (const float*)d_in[12 + off];
    const float* W_hh1 = (const float*)d_in[13 + off];
    const float* b_ih1 = (const float*)d_in[14 + off];
    const float* b_hh1 = (const float*)d_in[15 + off];
    const float* Wl    = (const float*)d_in[16 + off];
    const float* bl    = (const float*)d_in[17 + off];
    float* out = (float*)d_out;

    cudaFuncSetAttribute(k_persist, cudaFuncAttributeMaxDynamicSharedMemorySize, SMEM_BYTES);
    k_persist<<<GRID, NTHR, SMEM_BYTES>>>(ctx, tgt, h1_0, c1_0, h2_0, c2_0, emb,
                                          W_ih0, W_hh0, b_ih0, b_hh0,
                                          W_ih1, W_hh1, b_ih1, b_hh1,
                                          Wl, bl, out, out_size);
}

// round 6
// speedup vs baseline: 1.6012x; 1.6012x over previous
#include <cuda_runtime.h>
#include <cuda_bf16.h>

#define NB 64
#define NS 500
#define NH 512
#define NV 3
#define NT 500
#define GRID 128
#define NTHR 256

// ---- smem layout (floats) ----
#define W1T_OFF 0               // [1536][16]  = 24576 fl (lstm1 weights, transposed)
#define W2T_OFF 24576           // [1024][16]  = 16384 fl (lstm2 weights, transposed)
#define WORK_OFF 40960          // 14336 fl: attn = 2 tile bufs of 7x1024; lstm xs = [32][64]
#define H2_OFF  55296           // 512
#define S0_OFF  55808           // 64
#define S1_OFF  55872           // 64
#define SC_OFF  55936           // 8
#define WTS_OFF 55944           // 8
#define CTL_OFF 55952           // 4
#define LG_OFF  55956           // 4
#define SMEM_FLOATS 55968
#define SMEM_BYTES (SMEM_FLOATS * 4 + 128)   // ~224 KB

#define ATR 7                   // attention tile rows
#define ATNT 36                 // ceil(250/7)

// ---------------- device state ----------------
__device__ __align__(16) float g_apart[2][NB][1024];
__device__ float g_m[NB][2];
__device__ float g_l[NB][2];
__device__ __align__(16) float g_h1[2][NB][NH];
__device__ __align__(16) float g_c1[NB][NH];
__device__ __align__(16) float g_h2[2][NB][NH];
__device__ __align__(16) float g_c2[NB][NH];
__device__ __align__(16) float g_E[NV][4][NH];
__device__ __align__(16) float g_B2[4][NH];
__device__ int g_idx[NB];

__device__ unsigned g_count = 0;
__device__ volatile unsigned g_epoch = 0;

__device__ __forceinline__ void gbar() {
    __threadfence();
    __syncthreads();
    if (threadIdx.x == 0) {
        unsigned e = g_epoch;
        if (atomicAdd(&g_count, 1) == GRID - 1) {
            g_count = 0;
            __threadfence();
            g_epoch = e + 1;
        } else {
            while (g_epoch == e) { __nanosleep(64); }
        }
        __threadfence();
    }
    __syncthreads();
}

__device__ __forceinline__ float2 ffma2(float2 a, float2 b, float2 c) {
    float2 d;
    asm("fma.rn.f32x2 %0, %1, %2, %3;"
        : "=l"(*reinterpret_cast<unsigned long long*>(&d))
        : "l"(*reinterpret_cast<unsigned long long*>(&a)),
          "l"(*reinterpret_cast<unsigned long long*>(&b)),
          "l"(*reinterpret_cast<unsigned long long*>(&c)));
    return d;
}

__device__ __forceinline__ float sigm(float x) { return 1.f / (1.f + expf(-x)); }

__device__ __forceinline__ void cpasync16(float* dst, const float* src) {
    unsigned sa = (unsigned)__cvta_generic_to_shared(dst);
    asm volatile("cp.async.cg.shared.global [%0], [%1], 16;" :: "r"(sa), "l"(src));
}

// ---------------- attention (cp.async flash, 7-row tiles) ----------------
__device__ void attn_phase(const float* __restrict__ ctx, const float* __restrict__ Wl,
                           const float* __restrict__ blv, float* __restrict__ out,
                           int t, int blk, float* smem) {
    int p = t & 1;
    int b = blk >> 1, h = blk & 1;
    int tid = threadIdx.x;
    int warp = tid >> 5, lane = tid & 31;
    float* tiles = smem + WORK_OFF;
    float* h2s = smem + H2_OFF;
    float* sc  = smem + SC_OFF;
    float* wts = smem + WTS_OFF;
    float* ctl = smem + CTL_OFF;
    float* lg  = smem + LG_OFF;

    const float* h2g = g_h2[p][b];
    ((float2*)h2s)[tid] = ((const float2*)h2g)[tid];
    if (tid == 0) { ctl[1] = -1e30f; ctl[2] = 0.f; }

    const float* gbase = ctx + ((size_t)(b * NS + h * 250)) * 1024;
    // prefetch tile 0 early (overlaps logits work)
    if (t < NT) {
        for (int c = tid; c < ATR * 256; c += 256)
            cpasync16(tiles + c * 4, gbase + c * 4);
        asm volatile("cp.async.commit_group;");
    }

    // ---- logits / argmax / log_softmax for step t-1 ----
    if (h == 0 && t > 0) {
        if (warp < 3) {
            const float* wr = Wl + warp * 512;
            float s = 0.f;
            for (int i = lane; i < 512; i += 32) s += wr[i] * h2g[i];
            for (int o = 16; o; o >>= 1) s += __shfl_xor_sync(0xffffffffu, s, o);
            if (!lane) lg[warp] = s + blv[warp];
        }
        __syncthreads();
        if (tid == 0) {
            float l0 = lg[0], l1 = lg[1], l2 = lg[2];
            int bi = 0; float bv = l0;
            if (l1 > bv) { bv = l1; bi = 1; }
            if (l2 > bv) { bv = l2; bi = 2; }
            g_idx[b] = bi;
            float lse = bv + logf(expf(l0 - bv) + expf(l1 - bv) + expf(l2 - bv));
            float* o = out + ((size_t)b * NT + (t - 1)) * 3;
            o[0] = l0 - lse; o[1] = l1 - lse; o[2] = l2 - lse;
        }
        __syncthreads();
    }
    if (t >= NT) return;

    float4 acc = make_float4(0.f, 0.f, 0.f, 0.f);

    for (int tt = 0; tt < ATNT; tt++) {
        int row0 = tt * ATR;
        int cnt = (250 - row0 < ATR) ? (250 - row0) : ATR;
        float* tb = tiles + (tt & 1) * (ATR * 1024);

        if (tt + 1 < ATNT) {
            int r1 = row0 + ATR;
            int c1 = (250 - r1 < ATR) ? (250 - r1) : ATR;
            float* dst = tiles + ((tt + 1) & 1) * (ATR * 1024);
            const float* src = gbase + (size_t)r1 * 1024;
            for (int c = tid; c < c1 * 256; c += 256)
                cpasync16(dst + c * 4, src + c * 4);
            asm volatile("cp.async.commit_group;");
            asm volatile("cp.async.wait_group 1;");
        } else {
            asm volatile("cp.async.wait_group 0;");
        }
        __syncthreads();

        // scores: warp w handles row w (ATR=7 < 8 warps)
        if (warp < cnt) {
            const float4* row = (const float4*)(tb + warp * 1024);
            const float4* hh = (const float4*)h2s;
            float s = 0.f;
#pragma unroll
            for (int i = 0; i < 8; i++) {
                float4 cv = row[lane + 32 * i];
                float4 hv = hh[lane + 32 * (i & 3)];
                s += cv.x * hv.x + cv.y * hv.y + cv.z * hv.z + cv.w * hv.w;
            }
            for (int o = 16; o; o >>= 1) s += __shfl_xor_sync(0xffffffffu, s, o);
            if (!lane) sc[warp] = s;
        }
        __syncthreads();

        if (warp == 0) {
            float sv = (lane < cnt) ? sc[lane] : -1e30f;
            float mt = sv;
            for (int o = 16; o; o >>= 1) mt = fmaxf(mt, __shfl_xor_sync(0xffffffffu, mt, o));
            float mprev = ctl[1];
            float mnew = fmaxf(mprev, mt);
            float r = __expf(mprev - mnew);
            float w = (lane < cnt) ? __expf(sv - mnew) : 0.f;
            if (lane < 8) wts[lane] = w;
            float ws = w;
            for (int o = 16; o; o >>= 1) ws += __shfl_xor_sync(0xffffffffu, ws, o);
            if (!lane) {
                ctl[0] = r;
                ctl[1] = mnew;
                ctl[2] = ctl[2] * r + ws;
            }
        }
        __syncthreads();

        float rs = ctl[0];
        acc.x *= rs; acc.y *= rs; acc.z *= rs; acc.w *= rs;
#pragma unroll
        for (int r = 0; r < ATR; r++) {
            if (r < cnt) {
                float w = wts[r];
                float4 v = ((const float4*)(tb + r * 1024))[tid];
                acc.x += w * v.x; acc.y += w * v.y;
                acc.z += w * v.z; acc.w += w * v.w;
            }
        }
        __syncthreads();
    }

    ((float4*)g_apart[h][b])[tid] = acc;
    if (tid == 0) { g_m[b][h] = ctl[1]; g_l[b][h] = ctl[2]; }
}

// ---------------- LSTM 1: smem weights + pipelined x ----------------
__device__ void lstm1_phase(int t, int cb, float* smem) {
    int p = t & 1, q = p ^ 1;
    int tid = threadIdx.x;
    float* s0s = smem + S0_OFF;
    float* s1s = smem + S1_OFF;
    float (*xs)[64] = (float(*)[64])(smem + WORK_OFF);
    const float4* wp = (const float4*)(smem + W1T_OFF);

    if (tid < 64) {
        float m0 = g_m[tid][0], m1 = g_m[tid][1];
        float M = fmaxf(m0, m1);
        float e0 = __expf(m0 - M), e1 = __expf(m1 - M);
        float L = g_l[tid][0] * e0 + g_l[tid][1] * e1;
        s0s[tid] = e0 / L; s1s[tid] = e1 / L;
    }
    __syncthreads();

    int b = tid & 63, jj = tid >> 6;
    int j0 = cb * 4 + jj;
    int vv = g_idx[b];
    float2 a01 = make_float2(g_E[vv][0][j0], g_E[vv][1][j0]);
    float2 a23 = make_float2(g_E[vv][2][j0], g_E[vv][3][j0]);

    int bq = tid >> 2;
    int kg = (tid & 3) * 8;
    float s0 = s0s[bq], s1 = s1s[bq];

    float4 x0a, x0b, x1a, x1b;
    x1a = make_float4(0.f, 0.f, 0.f, 0.f);
    x1b = make_float4(0.f, 0.f, 0.f, 0.f);
    // preload kt=0
    {
        int k = kg;
        x0a = *(const float4*)&g_apart[0][bq][k];
        x0b = *(const float4*)&g_apart[0][bq][k + 4];
        x1a = *(const float4*)&g_apart[1][bq][k];
        x1b = *(const float4*)&g_apart[1][bq][k + 4];
    }

    for (int kt = 0; kt < 48; kt++) {
        int kb = kt * 32;
        __syncthreads();   // xs free
        if (kb < 1024) {
            xs[kg + 0][bq] = s0 * x0a.x + s1 * x1a.x;
            xs[kg + 1][bq] = s0 * x0a.y + s1 * x1a.y;
            xs[kg + 2][bq] = s0 * x0a.z + s1 * x1a.z;
            xs[kg + 3][bq] = s0 * x0a.w + s1 * x1a.w;
            xs[kg + 4][bq] = s0 * x0b.x + s1 * x1b.x;
            xs[kg + 5][bq] = s0 * x0b.y + s1 * x1b.y;
            xs[kg + 6][bq] = s0 * x0b.z + s1 * x1b.z;
            xs[kg + 7][bq] = s0 * x0b.w + s1 * x1b.w;
        } else {
            xs[kg + 0][bq] = x0a.x; xs[kg + 1][bq] = x0a.y;
            xs[kg + 2][bq] = x0a.z; xs[kg + 3][bq] = x0a.w;
            xs[kg + 4][bq] = x0b.x; xs[kg + 5][bq] = x0b.y;
            xs[kg + 6][bq] = x0b.z; xs[kg + 7][bq] = x0b.w;
        }
        // issue next tile's loads (latency hidden under FMA below)
        if (kt + 1 < 48) {
            int kn = (kt + 1) * 32 + kg;
            if (kn < 1024) {
                x0a = *(const float4*)&g_apart[0][bq][kn];
                x0b = *(const float4*)&g_apart[0][bq][kn + 4];
                x1a = *(const float4*)&g_apart[1][bq][kn];
                x1b = *(const float4*)&g_apart[1][bq][kn + 4];
            } else {
                x0a = *(const float4*)&g_h1[p][bq][kn - 1024];
                x0b = *(const float4*)&g_h1[p][bq][kn - 1020];
            }
        }
        __syncthreads();   // xs ready
#pragma unroll
        for (int k = 0; k < 32; k++) {
            float x = xs[k][b];
            float4 w4 = wp[(kb + k) * 4 + jj];
            float2 xx = make_float2(x, x);
            a01 = ffma2(make_float2(w4.x, w4.y), xx, a01);
            a23 = ffma2(make_float2(w4.z, w4.w), xx, a23);
        }
    }
    float si = sigm(a01.x), sf = sigm(a01.y), so = sigm(a23.y);
    float tg = tanhf(a23.x);
    float cn = sf * g_c1[b][j0] + si * tg;
    float hn = so * tanhf(cn);
    g_c1[b][j0] = cn;
    g_h1[q][b][j0] = hn;
}

// ---------------- LSTM 2: smem weights + pipelined x ----------------
__device__ void lstm2_phase(int t, int cb, float* smem) {
    int p = t & 1, q = p ^ 1;
    int tid = threadIdx.x;
    float (*xs)[64] = (float(*)[64])(smem + WORK_OFF);
    const float4* wp = (const float4*)(smem + W2T_OFF);

    int b = tid & 63, jj = tid >> 6;
    int j0 = cb * 4 + jj;
    float2 a01 = make_float2(g_B2[0][j0], g_B2[1][j0]);
    float2 a23 = make_float2(g_B2[2][j0], g_B2[3][j0]);

    int bq = tid >> 2;
    int kg = (tid & 3) * 8;

    float4 x0a, x0b;
    x0a = *(const float4*)&g_h1[q][bq][kg];
    x0b = *(const float4*)&g_h1[q][bq][kg + 4];

    for (int kt = 0; kt < 32; kt++) {
        int kb = kt * 32;
        __syncthreads();
        xs[kg + 0][bq] = x0a.x; xs[kg + 1][bq] = x0a.y;
        xs[kg + 2][bq] = x0a.z; xs[kg + 3][bq] = x0a.w;
        xs[kg + 4][bq] = x0b.x; xs[kg + 5][bq] = x0b.y;
        xs[kg + 6][bq] = x0b.z; xs[kg + 7][bq] = x0b.w;
        if (kt + 1 < 32) {
            int kn = (kt + 1) * 32 + kg;
            const float* src = (kn < 512) ? &g_h1[q][bq][kn] : &g_h2[p][bq][kn - 512];
            x0a = *(const float4*)src;
            x0b = *(const float4*)(src + 4);
        }
        __syncthreads();
#pragma unroll
        for (int k = 0; k < 32; k++) {
            float x = xs[k][b];
            float4 w4 = wp[(kb + k) * 4 + jj];
            float2 xx = make_float2(x, x);
            a01 = ffma2(make_float2(w4.x, w4.y), xx, a01);
            a23 = ffma2(make_float2(w4.z, w4.w), xx, a23);
        }
    }
    float si = sigm(a01.x), sf = sigm(a01.y), so = sigm(a23.y);
    float tg = tanhf(a23.x);
    float cn = sf * g_c2[b][j0] + si * tg;
    float hn = so * tanhf(cn);
    g_c2[b][j0] = cn;
    g_h2[q][b][j0] = hn;
}

// ---------------- persistent kernel ----------------
__global__ void __launch_bounds__(NTHR, 1)
k_persist(const float* __restrict__ ctx, const int* __restrict__ tgt,
          const float* __restrict__ h1_0, const float* __restrict__ c1_0,
          const float* __restrict__ h2_0, const float* __restrict__ c2_0,
          const float* __restrict__ emb,
          const float* __restrict__ W_ih0, const float* __restrict__ W_hh0,
          const float* __restrict__ b_ih0, const float* __restrict__ b_hh0,
          const float* __restrict__ W_ih1, const float* __restrict__ W_hh1,
          const float* __restrict__ b_ih1, const float* __restrict__ b_hh1,
          const float* __restrict__ Wl, const float* __restrict__ blv,
          float* __restrict__ out, int out_size) {
    extern __shared__ __align__(16) float smem[];
    int blk = blockIdx.x;
    int tid = threadIdx.x;
    int warp = tid >> 5, lane = tid & 31;

    // ---- setup ----
    {
        int gi = blk * NTHR + tid;
        ((float*)g_h1[0])[gi] = h1_0[gi];
        ((float*)g_c1)[gi]    = c1_0[gi];
        ((float*)g_h2[0])[gi] = h2_0[gi];
        ((float*)g_c2)[gi]    = c2_0[gi];
        if (gi < 4 * NH) ((float*)g_B2)[gi] = b_ih1[gi] + b_hh1[gi];
        if (blk == 0 && tid < NB) g_idx[tid] = tgt[tid * NT];
        for (int r = blk * 8 + warp; r < NV * 2048; r += GRID * 8) {
            int v = r / 2048, row = r % 2048;
            const float* wr = W_ih0 + (size_t)row * 1536;
            const float* ev = emb + v * 512;
            float s = 0.f;
            for (int i = lane; i < 512; i += 32) s += wr[i] * ev[i];
            for (int o = 16; o; o >>= 1) s += __shfl_xor_sync(0xffffffffu, s, o);
            if (!lane) g_E[v][row >> 9][row & 511] = s + b_ih0[row] + b_hh0[row];
        }
        // weight slices -> smem (transposed: minor index r = jj*4 + g)
        int cb = blk;
#pragma unroll 1
        for (int r = 0; r < 16; r++) {
            int g = r & 3, jj = r >> 2;
            int row = g * 512 + cb * 4 + jj;
            for (int k = tid; k < 1536; k += NTHR) {
                float v = (k < 1024) ? W_ih0[(size_t)row * 1536 + 512 + k]
                                     : W_hh0[(size_t)row * 512 + (k - 1024)];
                smem[W1T_OFF + k * 16 + r] = v;
            }
            for (int k = tid; k < 1024; k += NTHR) {
                float v = (k < 512) ? W_ih1[(size_t)row * 512 + k]
                                    : W_hh1[(size_t)row * 512 + (k - 512)];
                smem[W2T_OFF + k * 16 + r] = v;
            }
        }
    }
    gbar();

    for (int t = 0; t <= NT; t++) {
        attn_phase(ctx, Wl, blv, out, t, blk, smem);
        if (t == NT) break;
        gbar();
        lstm1_phase(t, blk, smem);
        gbar();
        lstm2_phase(t, blk, smem);
        gbar();
    }

    if (out_size >= NB * NT * NV + NB * NT) {
        int i = blk * NTHR + tid;
        if (i < NB * NT) out[NB * NT * NV + i] = (float)tgt[i];
    }
}

// ---------------- launch ----------------
extern "C" void kernel_launch(void* const* d_in, const int* in_sizes, int n_in,
                              void* d_out, int out_size) {
    int off = (n_in >= 18) ? 0 : -1;
    const float* ctx   = (const float*)d_in[0];
    const int*   tgt   = (const int*)d_in[1];
    const float* h1_0  = (const float*)d_in[3 + off];
    const float* c1_0  = (const float*)d_in[4 + off];
    const float* h2_0  = (const float*)d_in[5 + off];
    const float* c2_0  = (const float*)d_in[6 + off];
    const float* emb   = (const float*)d_in[7 + off];
    const float* W_ih0 = (const float*)d_in[8 + off];
    const float* W_hh0 = (const float*)d_in[9 + off];
    const float* b_ih0 = (const float*)d_in[10 + off];
    const float* b_hh0 = (const float*)d_in[11 + off];
    const float* W_ih1 = (const float*)d_in[12 + off];
    const float* W_hh1 = (const float*)d_in[13 + off];
    const float* b_ih1 = (const float*)d_in[14 + off];
    const float* b_hh1 = (const float*)d_in[15 + off];
    const float* Wl    = (const float*)d_in[16 + off];
    const float* bl    = (const float*)d_in[17 + off];
    float* out = (float*)d_out;

    cudaFuncSetAttribute(k_persist, cudaFuncAttributeMaxDynamicSharedMemorySize, SMEM_BYTES);
    k_persist<<<GRID, NTHR, SMEM_BYTES>>>(ctx, tgt, h1_0, c1_0, h2_0, c2_0, emb,
                                          W_ih0, W_hh0, b_ih0, b_hh0,
                                          W_ih1, W_hh1, b_ih1, b_hh1,
                                          Wl, bl, out, out_size);
}

// round 7
// speedup vs baseline: 1.6795x; 1.0489x over previous
#include <cuda_runtime.h>
#include <cuda_bf16.h>
#include <cstdio>

#define NB 64
#define NS 500
#define NH 512
#define NV 3
#define NT 500
#define GRID 128
#define NTHR 256

// ---- smem layout (floats) ----
#define W1T_OFF 0               // [1536][16]  = 24576 fl (lstm1 weights, transposed)
#define W2T_OFF 24576           // [1024][16]  = 16384 fl (lstm2 weights, transposed)
#define WORK_OFF 40960          // 14336 fl: attn = 2 tile bufs of 7x1024; lstm xs = [32][64]
#define H2_OFF  55296           // 512
#define S0_OFF  55808           // 64
#define S1_OFF  55872           // 64
#define SC_OFF  55936           // 8
#define LG_OFF  55944           // 4
#define SMEM_FLOATS 55952
#define SMEM_BYTES (SMEM_FLOATS * 4 + 128)   // ~224 KB

#define ATR 7                   // attention tile rows
#define ATNT 36                 // ceil(250/7)

// ---------------- device state ----------------
__device__ __align__(16) float g_apart[2][NB][1024];
__device__ float g_m[NB][2];
__device__ float g_l[NB][2];
__device__ __align__(16) float g_h1[2][NB][NH];
__device__ __align__(16) float g_c1[NB][NH];
__device__ __align__(16) float g_h2[2][NB][NH];
__device__ __align__(16) float g_c2[NB][NH];
__device__ __align__(16) float g_E[NV][4][NH];
__device__ __align__(16) float g_B2[4][NH];
__device__ int g_idx[NB];

__device__ unsigned g_count = 0;
__device__ volatile unsigned g_epoch = 0;

__device__ __forceinline__ void gbar() {
    __threadfence();
    __syncthreads();
    if (threadIdx.x == 0) {
        unsigned e = g_epoch;
        if (atomicAdd(&g_count, 1) == GRID - 1) {
            g_count = 0;
            __threadfence();
            g_epoch = e + 1;
        } else {
            while (g_epoch == e) { __nanosleep(64); }
        }
        __threadfence();
    }
    __syncthreads();
}

__device__ __forceinline__ float2 ffma2(float2 a, float2 b, float2 c) {
    float2 d;
    asm("fma.rn.f32x2 %0, %1, %2, %3;"
        : "=l"(*reinterpret_cast<unsigned long long*>(&d))
        : "l"(*reinterpret_cast<unsigned long long*>(&a)),
          "l"(*reinterpret_cast<unsigned long long*>(&b)),
          "l"(*reinterpret_cast<unsigned long long*>(&c)));
    return d;
}

__device__ __forceinline__ float sigm(float x) { return 1.f / (1.f + expf(-x)); }

__device__ __forceinline__ void cpasync16(float* dst, const float* src) {
    unsigned sa = (unsigned)__cvta_generic_to_shared(dst);
    asm volatile("cp.async.cg.shared.global [%0], [%1], 16;" :: "r"(sa), "l"(src));
}

// ---------------- attention (cp.async flash, redundant per-thread softmax) ----
__device__ void attn_phase(const float* __restrict__ ctx, const float* __restrict__ Wl,
                           const float* __restrict__ blv, float* __restrict__ out,
                           int t, int blk, float* smem) {
    int p = t & 1;
    int b = blk >> 1, h = blk & 1;
    int tid = threadIdx.x;
    int warp = tid >> 5, lane = tid & 31;
    float* tiles = smem + WORK_OFF;
    float* h2s = smem + H2_OFF;
    float* sc  = smem + SC_OFF;
    float* lg  = smem + LG_OFF;

    const float* h2g = g_h2[p][b];
    ((float2*)h2s)[tid] = ((const float2*)h2g)[tid];

    const float* gbase = ctx + ((size_t)(b * NS + h * 250)) * 1024;
    // prefetch tile 0 early (overlaps logits work)
    if (t < NT) {
        for (int c = tid; c < ATR * 256; c += 256)
            cpasync16(tiles + c * 4, gbase + c * 4);
        asm volatile("cp.async.commit_group;");
    }

    // ---- logits / argmax / log_softmax for step t-1 ----
    if (h == 0 && t > 0) {
        if (warp < 3) {
            const float* wr = Wl + warp * 512;
            float s = 0.f;
            for (int i = lane; i < 512; i += 32) s += wr[i] * h2g[i];
            for (int o = 16; o; o >>= 1) s += __shfl_xor_sync(0xffffffffu, s, o);
            if (!lane) lg[warp] = s + blv[warp];
        }
        __syncthreads();
        if (tid == 0) {
            float l0 = lg[0], l1 = lg[1], l2 = lg[2];
            int bi = 0; float bv = l0;
            if (l1 > bv) { bv = l1; bi = 1; }
            if (l2 > bv) { bv = l2; bi = 2; }
            g_idx[b] = bi;
            float lse = bv + logf(expf(l0 - bv) + expf(l1 - bv) + expf(l2 - bv));
            float* o = out + ((size_t)b * NT + (t - 1)) * 3;
            o[0] = l0 - lse; o[1] = l1 - lse; o[2] = l2 - lse;
        }
        __syncthreads();
    }
    if (t >= NT) return;

    float4 acc = make_float4(0.f, 0.f, 0.f, 0.f);
    float m_run = -1e30f, l_run = 0.f;   // identical in every thread

    for (int tt = 0; tt < ATNT; tt++) {
        int row0 = tt * ATR;
        int cnt = (250 - row0 < ATR) ? (250 - row0) : ATR;
        float* tb = tiles + (tt & 1) * (ATR * 1024);

        if (tt + 1 < ATNT) {
            int r1 = row0 + ATR;
            int c1 = (250 - r1 < ATR) ? (250 - r1) : ATR;
            float* dst = tiles + ((tt + 1) & 1) * (ATR * 1024);
            const float* src = gbase + (size_t)r1 * 1024;
            for (int c = tid; c < c1 * 256; c += 256)
                cpasync16(dst + c * 4, src + c * 4);
            asm volatile("cp.async.commit_group;");
            asm volatile("cp.async.wait_group 1;");
        } else {
            asm volatile("cp.async.wait_group 0;");
        }
        __syncthreads();               // tile ready for all threads

        // scores: warp w handles row w (ATR=7 < 8 warps)
        if (warp < cnt) {
            const float4* row = (const float4*)(tb + warp * 1024);
            const float4* hh = (const float4*)h2s;
            float s = 0.f;
#pragma unroll
            for (int i = 0; i < 8; i++) {
                float4 cv = row[lane + 32 * i];
                float4 hv = hh[lane + 32 * (i & 3)];
                s += cv.x * hv.x + cv.y * hv.y + cv.z * hv.z + cv.w * hv.w;
            }
            for (int o = 16; o; o >>= 1) s += __shfl_xor_sync(0xffffffffu, s, o);
            if (!lane) sc[warp] = s;
        }
        __syncthreads();               // scores visible

        // redundant per-thread softmax bookkeeping (identical in all threads)
        float w[ATR];
        float mt = -1e30f;
#pragma unroll
        for (int r = 0; r < ATR; r++) if (r < cnt) mt = fmaxf(mt, sc[r]);
        float mnew = fmaxf(m_run, mt);
        float rs = __expf(m_run - mnew);
        float ws = 0.f;
#pragma unroll
        for (int r = 0; r < ATR; r++) {
            if (r < cnt) { w[r] = __expf(sc[r] - mnew); ws += w[r]; }
            else w[r] = 0.f;
        }
        m_run = mnew;
        l_run = l_run * rs + ws;

        acc.x *= rs; acc.y *= rs; acc.z *= rs; acc.w *= rs;
#pragma unroll
        for (int r = 0; r < ATR; r++) {
            if (r < cnt) {
                float wr = w[r];
                float4 v = ((const float4*)(tb + r * 1024))[tid];
                acc.x += wr * v.x; acc.y += wr * v.y;
                acc.z += wr * v.z; acc.w += wr * v.w;
            }
        }
        __syncthreads();               // sc reuse + buffer overwrite guard
    }

    ((float4*)g_apart[h][b])[tid] = acc;
    if (tid == 0) { g_m[b][h] = m_run; g_l[b][h] = l_run; }
}

// ---------------- LSTM 1: smem weights + pipelined x ----------------
__device__ void lstm1_phase(int t, int cb, float* smem) {
    int p = t & 1, q = p ^ 1;
    int tid = threadIdx.x;
    float* s0s = smem + S0_OFF;
    float* s1s = smem + S1_OFF;
    float (*xs)[64] = (float(*)[64])(smem + WORK_OFF);
    const float4* wp = (const float4*)(smem + W1T_OFF);

    if (tid < 64) {
        float m0 = g_m[tid][0], m1 = g_m[tid][1];
        float M = fmaxf(m0, m1);
        float e0 = __expf(m0 - M), e1 = __expf(m1 - M);
        float L = g_l[tid][0] * e0 + g_l[tid][1] * e1;
        s0s[tid] = e0 / L; s1s[tid] = e1 / L;
    }
    __syncthreads();

    int b = tid & 63, jj = tid >> 6;
    int j0 = cb * 4 + jj;
    int vv = g_idx[b];
    float2 a01 = make_float2(g_E[vv][0][j0], g_E[vv][1][j0]);
    float2 a23 = make_float2(g_E[vv][2][j0], g_E[vv][3][j0]);

    int bq = tid >> 2;
    int kg = (tid & 3) * 8;
    float s0 = s0s[bq], s1 = s1s[bq];

    float4 x0a, x0b, x1a, x1b;
    x1a = make_float4(0.f, 0.f, 0.f, 0.f);
    x1b = make_float4(0.f, 0.f, 0.f, 0.f);
    {
        int k = kg;
        x0a = *(const float4*)&g_apart[0][bq][k];
        x0b = *(const float4*)&g_apart[0][bq][k + 4];
        x1a = *(const float4*)&g_apart[1][bq][k];
        x1b = *(const float4*)&g_apart[1][bq][k + 4];
    }

    for (int kt = 0; kt < 48; kt++) {
        int kb = kt * 32;
        __syncthreads();   // xs free
        if (kb < 1024) {
            xs[kg + 0][bq] = s0 * x0a.x + s1 * x1a.x;
            xs[kg + 1][bq] = s0 * x0a.y + s1 * x1a.y;
            xs[kg + 2][bq] = s0 * x0a.z + s1 * x1a.z;
            xs[kg + 3][bq] = s0 * x0a.w + s1 * x1a.w;
            xs[kg + 4][bq] = s0 * x0b.x + s1 * x1b.x;
            xs[kg + 5][bq] = s0 * x0b.y + s1 * x1b.y;
            xs[kg + 6][bq] = s0 * x0b.z + s1 * x1b.z;
            xs[kg + 7][bq] = s0 * x0b.w + s1 * x1b.w;
        } else {
            xs[kg + 0][bq] = x0a.x; xs[kg + 1][bq] = x0a.y;
            xs[kg + 2][bq] = x0a.z; xs[kg + 3][bq] = x0a.w;
            xs[kg + 4][bq] = x0b.x; xs[kg + 5][bq] = x0b.y;
            xs[kg + 6][bq] = x0b.z; xs[kg + 7][bq] = x0b.w;
        }
        if (kt + 1 < 48) {
            int kn = (kt + 1) * 32 + kg;
            if (kn < 1024) {
                x0a = *(const float4*)&g_apart[0][bq][kn];
                x0b = *(const float4*)&g_apart[0][bq][kn + 4];
                x1a = *(const float4*)&g_apart[1][bq][kn];
                x1b = *(const float4*)&g_apart[1][bq][kn + 4];
            } else {
                x0a = *(const float4*)&g_h1[p][bq][kn - 1024];
                x0b = *(const float4*)&g_h1[p][bq][kn - 1020];
            }
        }
        __syncthreads();   // xs ready
#pragma unroll
        for (int k = 0; k < 32; k++) {
            float x = xs[k][b];
            float4 w4 = wp[(kb + k) * 4 + jj];
            float2 xx = make_float2(x, x);
            a01 = ffma2(make_float2(w4.x, w4.y), xx, a01);
            a23 = ffma2(make_float2(w4.z, w4.w), xx, a23);
        }
    }
    float si = sigm(a01.x), sf = sigm(a01.y), so = sigm(a23.y);
    float tg = tanhf(a23.x);
    float cn = sf * g_c1[b][j0] + si * tg;
    float hn = so * tanhf(cn);
    g_c1[b][j0] = cn;
    g_h1[q][b][j0] = hn;
}

// ---------------- LSTM 2: smem weights + pipelined x ----------------
__device__ void lstm2_phase(int t, int cb, float* smem) {
    int p = t & 1, q = p ^ 1;
    int tid = threadIdx.x;
    float (*xs)[64] = (float(*)[64])(smem + WORK_OFF);
    const float4* wp = (const float4*)(smem + W2T_OFF);

    int b = tid & 63, jj = tid >> 6;
    int j0 = cb * 4 + jj;
    float2 a01 = make_float2(g_B2[0][j0], g_B2[1][j0]);
    float2 a23 = make_float2(g_B2[2][j0], g_B2[3][j0]);

    int bq = tid >> 2;
    int kg = (tid & 3) * 8;

    float4 x0a, x0b;
    x0a = *(const float4*)&g_h1[q][bq][kg];
    x0b = *(const float4*)&g_h1[q][bq][kg + 4];

    for (int kt = 0; kt < 32; kt++) {
        int kb = kt * 32;
        __syncthreads();
        xs[kg + 0][bq] = x0a.x; xs[kg + 1][bq] = x0a.y;
        xs[kg + 2][bq] = x0a.z; xs[kg + 3][bq] = x0a.w;
        xs[kg + 4][bq] = x0b.x; xs[kg + 5][bq] = x0b.y;
        xs[kg + 6][bq] = x0b.z; xs[kg + 7][bq] = x0b.w;
        if (kt + 1 < 32) {
            int kn = (kt + 1) * 32 + kg;
            const float* src = (kn < 512) ? &g_h1[q][bq][kn] : &g_h2[p][bq][kn - 512];
            x0a = *(const float4*)src;
            x0b = *(const float4*)(src + 4);
        }
        __syncthreads();
#pragma unroll
        for (int k = 0; k < 32; k++) {
            float x = xs[k][b];
            float4 w4 = wp[(kb + k) * 4 + jj];
            float2 xx = make_float2(x, x);
            a01 = ffma2(make_float2(w4.x, w4.y), xx, a01);
            a23 = ffma2(make_float2(w4.z, w4.w), xx, a23);
        }
    }
    float si = sigm(a01.x), sf = sigm(a01.y), so = sigm(a23.y);
    float tg = tanhf(a23.x);
    float cn = sf * g_c2[b][j0] + si * tg;
    float hn = so * tanhf(cn);
    g_c2[b][j0] = cn;
    g_h2[q][b][j0] = hn;
}

// ---------------- persistent kernel ----------------
__global__ void __launch_bounds__(NTHR, 1)
k_persist(const float* __restrict__ ctx, const int* __restrict__ tgt,
          const float* __restrict__ h1_0, const float* __restrict__ c1_0,
          const float* __restrict__ h2_0, const float* __restrict__ c2_0,
          const float* __restrict__ emb,
          const float* __restrict__ W_ih0, const float* __restrict__ W_hh0,
          const float* __restrict__ b_ih0, const float* __restrict__ b_hh0,
          const float* __restrict__ W_ih1, const float* __restrict__ W_hh1,
          const float* __restrict__ b_ih1, const float* __restrict__ b_hh1,
          const float* __restrict__ Wl, const float* __restrict__ blv,
          float* __restrict__ out, int out_size) {
    extern __shared__ __align__(16) float smem[];
    int blk = blockIdx.x;
    int tid = threadIdx.x;
    int warp = tid >> 5, lane = tid & 31;

    // ---- setup ----
    {
        int gi = blk * NTHR + tid;
        ((float*)g_h1[0])[gi] = h1_0[gi];
        ((float*)g_c1)[gi]    = c1_0[gi];
        ((float*)g_h2[0])[gi] = h2_0[gi];
        ((float*)g_c2)[gi]    = c2_0[gi];
        if (gi < 4 * NH) ((float*)g_B2)[gi] = b_ih1[gi] + b_hh1[gi];
        if (blk == 0 && tid < NB) g_idx[tid] = tgt[tid * NT];
        for (int r = blk * 8 + warp; r < NV * 2048; r += GRID * 8) {
            int v = r / 2048, row = r % 2048;
            const float* wr = W_ih0 + (size_t)row * 1536;
            const float* ev = emb + v * 512;
            float s = 0.f;
            for (int i = lane; i < 512; i += 32) s += wr[i] * ev[i];
            for (int o = 16; o; o >>= 1) s += __shfl_xor_sync(0xffffffffu, s, o);
            if (!lane) g_E[v][row >> 9][row & 511] = s + b_ih0[row] + b_hh0[row];
        }
        int cb = blk;
#pragma unroll 1
        for (int r = 0; r < 16; r++) {
            int g = r & 3, jj = r >> 2;
            int row = g * 512 + cb * 4 + jj;
            for (int k = tid; k < 1536; k += NTHR) {
                float v = (k < 1024) ? W_ih0[(size_t)row * 1536 + 512 + k]
                                     : W_hh0[(size_t)row * 512 + (k - 1024)];
                smem[W1T_OFF + k * 16 + r] = v;
            }
            for (int k = tid; k < 1024; k += NTHR) {
                float v = (k < 512) ? W_ih1[(size_t)row * 512 + k]
                                    : W_hh1[(size_t)row * 512 + (k - 512)];
                smem[W2T_OFF + k * 16 + r] = v;
            }
        }
    }
    gbar();

    long long c_at = 0, c_b1 = 0, c_l1 = 0, c_b2 = 0, c_l2 = 0, c_b3 = 0;
    for (int t = 0; t <= NT; t++) {
        long long t0 = clock64();
        attn_phase(ctx, Wl, blv, out, t, blk, smem);
        long long t1 = clock64(); c_at += t1 - t0;
        if (t == NT) break;
        gbar();
        long long t2 = clock64(); c_b1 += t2 - t1;
        lstm1_phase(t, blk, smem);
        long long t3 = clock64(); c_l1 += t3 - t2;
        gbar();
        long long t4 = clock64(); c_b2 += t4 - t3;
        lstm2_phase(t, blk, smem);
        long long t5 = clock64(); c_l2 += t5 - t4;
        gbar();
        c_b3 += clock64() - t5;
    }

    if (blk == 0 && tid == 0)
        printf("PHASES attn=%lld bar1=%lld lstm1=%lld bar2=%lld lstm2=%lld bar3=%lld\n",
               c_at, c_b1, c_l1, c_b2, c_l2, c_b3);

    if (out_size >= NB * NT * NV + NB * NT) {
        int i = blk * NTHR + tid;
        if (i < NB * NT) out[NB * NT * NV + i] = (float)tgt[i];
    }
}

// ---------------- launch ----------------
extern "C" void kernel_launch(void* const* d_in, const int* in_sizes, int n_in,
                              void* d_out, int out_size) {
    int off = (n_in >= 18) ? 0 : -1;
    const float* ctx   = (const float*)d_in[0];
    const int*   tgt   = (const int*)d_in[1];
    const float* h1_0  = (const float*)d_in[3 + off];
    const float* c1_0  = (const float*)d_in[4 + off];
    const float* h2_0  = (const float*)d_in[5 + off];
    const float* c2_0  = (const float*)d_in[6 + off];
    const float* emb   = (const float*)d_in[7 + off];
    const float* W_ih0 = (const float*)d_in[8 + off];
    const float* W_hh0 = (const float*)d_in[9 + off];
    const float* b_ih0 = (const float*)d_in[10 + off];
    const float* b_hh0 = (const float*)d_in[11 + off];
    const float* W_ih1 = (const float*)d_in[12 + off];
    const float* W_hh1 = (const float*)d_in[13 + off];
    const float* b_ih1 = (const float*)d_in[14 + off];
    const float* b_hh1 = (const float*)d_in[15 + off];
    const float* Wl    = (const float*)d_in[16 + off];
    const float* bl    = (const float*)d_in[17 + off];
    float* out = (float*)d_out;

    cudaFuncSetAttribute(k_persist, cudaFuncAttributeMaxDynamicSharedMemorySize, SMEM_BYTES);
    k_persist<<<GRID, NTHR, SMEM_BYTES>>>(ctx, tgt, h1_0, c1_0, h2_0, c2_0, emb,
                                          W_ih0, W_hh0, b_ih0, b_hh0,
                                          W_ih1, W_hh1, b_ih1, b_hh1,
                                          Wl, bl, out, out_size);
}